// round 9
// baseline (speedup 1.0000x reference)
#include <cuda_runtime.h>
#include <cuda_fp16.h>
#include <math.h>
#include <cstdint>

#define VOCAB 4096
#define HID   512
#define BATCH 64
#define SEQ   512
#define MROWS (SEQ * BATCH)

typedef unsigned long long u64;

// ---------------- scratch (static device globals; no allocation) ----------------
__device__ float    g_WihT[VOCAB * HID];          // 8 MB  : W_ih transposed [V,H]
__device__ float    g_xproj[MROWS * HID];         // 64 MB : x_proj, layout [T,B,H]
__device__ float2   g_hseq[SEQ * 8 * 4 * 512];    // 64 MB : h states, pair-interleaved
__device__ __half   g_A16[MROWS * HID];           // 32 MB : fp16 of out_h
__device__ __half   g_B16[VOCAB * HID];           // 4 MB  : fp16 of W_fc
__device__ unsigned g_cnt[8];                     // per-batch-group barrier counters

// ======================= helpers =======================
__device__ __forceinline__ uint32_t smem_u32(const void* p) {
    uint32_t a;
    asm("{ .reg .u64 t; cvta.to.shared.u64 t, %1; cvt.u32.u64 %0, t; }" : "=r"(a) : "l"(p));
    return a;
}
__device__ __forceinline__ void cp16(uint32_t dst, const void* src) {
    asm volatile("cp.async.cg.shared.global [%0], [%1], 16;" :: "r"(dst), "l"(src));
}
#define CP_COMMIT() asm volatile("cp.async.commit_group;" ::: "memory")
#define CP_WAIT(n)  asm volatile("cp.async.wait_group %0;" :: "n"(n) : "memory")

__device__ __forceinline__ void ldm_x4(uint32_t& r0, uint32_t& r1, uint32_t& r2,
                                       uint32_t& r3, uint32_t a) {
    asm volatile("ldmatrix.sync.aligned.m8n8.x4.shared.b16 {%0,%1,%2,%3}, [%4];"
                 : "=r"(r0), "=r"(r1), "=r"(r2), "=r"(r3) : "r"(a));
}
__device__ __forceinline__ void mma16816(float* c, uint32_t a0, uint32_t a1,
                                         uint32_t a2, uint32_t a3,
                                         uint32_t b0, uint32_t b1) {
    asm volatile("mma.sync.aligned.m16n8k16.row.col.f32.f16.f16.f32 "
                 "{%0,%1,%2,%3}, {%4,%5,%6,%7}, {%8,%9}, {%0,%1,%2,%3};"
                 : "+f"(c[0]), "+f"(c[1]), "+f"(c[2]), "+f"(c[3])
                 : "r"(a0), "r"(a1), "r"(a2), "r"(a3), "r"(b0), "r"(b1));
}

// ---- packed fp32x2 ----
__device__ __forceinline__ u64 pack2(float x, float y) {
    u64 r; asm("mov.b64 %0, {%1, %2};" : "=l"(r) : "f"(x), "f"(y)); return r;
}
__device__ __forceinline__ float2 unpack2(u64 v) {
    float2 f; asm("mov.b64 {%0, %1}, %2;" : "=f"(f.x), "=f"(f.y) : "l"(v)); return f;
}
__device__ __forceinline__ void fma2(u64& acc, u64 a, u64 b) {
    asm("fma.rn.f32x2 %0, %1, %2, %0;" : "+l"(acc) : "l"(a), "l"(b));
}
__device__ __forceinline__ u64 add2(u64 a, u64 b) {
    u64 r; asm("add.rn.f32x2 %0, %1, %2;" : "=l"(r) : "l"(a), "l"(b)); return r;
}

// ---------------- transpose W_ih [H,V] -> g_WihT [V,H] ----------------
__global__ void k_transpose(const float* __restrict__ Wih) {
    __shared__ float tile[32][33];
    int v0 = blockIdx.x * 32;
    int h0 = blockIdx.y * 32;
    int tx = threadIdx.x, ty = threadIdx.y;   // 32 x 8
    #pragma unroll
    for (int i = ty; i < 32; i += 8)
        tile[i][tx] = Wih[(h0 + i) * VOCAB + v0 + tx];
    __syncthreads();
    #pragma unroll
    for (int i = ty; i < 32; i += 8)
        g_WihT[(v0 + i) * HID + h0 + tx] = tile[tx][i];
}

// ---------------- gather + bias ----------------
__global__ void k_gather(const int* __restrict__ inp,
                         const float* __restrict__ b_ih,
                         const float* __restrict__ b_hh) {
    int row = blockIdx.x;              // row = t*BATCH + b
    int t = row / BATCH;
    int b = row % BATCH;
    int tok = inp[b * SEQ + t];
    const float4* src = (const float4*)&g_WihT[tok * HID];
    const float4* bi4 = (const float4*)b_ih;
    const float4* bh4 = (const float4*)b_hh;
    float4* dst = (float4*)&g_xproj[row * HID];
    int i = threadIdx.x;               // 128 threads
    float4 v = src[i];
    float4 bi = bi4[i], bh = bh4[i];
    v.x += bi.x + bh.x;  v.y += bi.y + bh.y;
    v.z += bi.z + bh.z;  v.w += bi.w + bh.w;
    dst[i] = v;
}

__global__ void k_reset() {
    if (threadIdx.x < 8) g_cnt[threadIdx.x] = 0;
}

// ---------------- recurrence v4: 2-way group interleave ----------------
// 64 CTAs x 256 threads. CTA(bx): jg = bx & 15 (j-slice of 32), gp = bx >> 4;
// handles batch groups gp and gp+4, alternating phases each step so each group's
// 16-CTA barrier latency is hidden behind the other group's compute.
// smem: Ws2 float2[256][32] 64KB + hp[2] float2[4*512] 32KB + part u64[8*4*32] 8KB.
extern "C" __global__ void __launch_bounds__(256, 1)
k_rnn(const float* __restrict__ Whh, const float* __restrict__ h0g) {
    extern __shared__ float sm[];
    float2* Ws2  = (float2*)sm;                   // [k/2][j] : (W[k][j], W[k+1][j])
    float2* hpA  = (float2*)(sm + 2 * 256 * 32);  // [pair][k] 4*512
    float2* hpB  = hpA + 4 * 512;
    u64*    part = (u64*)(hpB + 4 * 512);         // [warp*4+pair][jl]

    int bx = blockIdx.x;
    int jg = bx & 15;
    int gp = bx >> 4;                 // 0..3
    int bgA = gp, bgB = gp + 4;
    int B0A = bgA * 8, B0B = bgB * 8;
    int J0 = jg * 32;
    int tid = threadIdx.x;
    int w = tid >> 5, jl = tid & 31;  // 8 warps, k-range 64 each
    int kbase = w * 64;

    // load W_hh slice as paired [k2][j]
    for (int idx = tid; idx < 256 * 32; idx += 256) {
        int j = idx & 31, k2 = idx >> 5;
        const float* wr = Whh + (J0 + j) * HID + 2 * k2;
        Ws2[idx] = make_float2(wr[0], wr[1]);
    }
    __syncthreads();

    // one phase: partials + reduce + store + arrive for one group
    auto phase = [&](float2* hp, int B0, int bg, int t) {
        u64 accA[4] = {0, 0, 0, 0}, accB[4] = {0, 0, 0, 0};
        const float2* w2 = Ws2 + (kbase >> 1) * 32 + jl;
        const ulonglong2* h2 = ((const ulonglong2*)hp) + (kbase >> 1);
        #pragma unroll 4
        for (int i = 0; i < 32; i++) {
            float2 wv = w2[i * 32];
            u64 w00 = pack2(wv.x, wv.x), w11 = pack2(wv.y, wv.y);
            #pragma unroll
            for (int p = 0; p < 4; p++) {
                ulonglong2 hv = h2[p * 256];
                fma2(accA[p], hv.x, w00);
                fma2(accB[p], hv.y, w11);
            }
            h2 += 1;
        }
        #pragma unroll
        for (int p = 0; p < 4; p++)
            part[(w * 4 + p) * 32 + jl] = add2(accA[p], accB[p]);
        __syncthreads();

        if (tid < 128) {
            int p = tid >> 5, j2 = tid & 31;
            u64 s = part[p * 32 + j2];
            #pragma unroll
            for (int ww = 1; ww < 8; ww++)
                s = add2(s, part[(ww * 4 + p) * 32 + j2]);
            float2 sv = unpack2(s);
            int b0g = B0 + 2 * p;
            size_t xb = ((size_t)t * BATCH + b0g) * HID + J0 + j2;
            float r0 = tanhf(sv.x + g_xproj[xb]);
            float r1 = tanhf(sv.y + g_xproj[xb + HID]);
            g_hseq[((size_t)(t * 8 + bg) * 4 + p) * 512 + (J0 + j2)] = make_float2(r0, r1);
            g_A16[xb]       = __float2half_rn(r0);
            g_A16[xb + HID] = __float2half_rn(r1);
        }
        __syncthreads();
        if (t < SEQ - 1 && tid == 0) {
            asm volatile("fence.acq_rel.gpu;" ::: "memory");
            asm volatile("red.relaxed.gpu.global.add.u32 [%0], %1;"
                         :: "l"(&g_cnt[bg]), "r"(1u) : "memory");
        }
        __syncthreads();
    };

    for (int t = 0; t < SEQ; t++) {
        // ---- wait for both groups' previous step, then stage both h buffers ----
        if (t == 0) {
            for (int idx = tid; idx < 2048; idx += 256) {
                int p = idx >> 9, k = idx & 511;
                hpA[p * 512 + k] = make_float2(h0g[(B0A + 2 * p) * HID + k],
                                               h0g[(B0A + 2 * p + 1) * HID + k]);
                hpB[p * 512 + k] = make_float2(h0g[(B0B + 2 * p) * HID + k],
                                               h0g[(B0B + 2 * p + 1) * HID + k]);
            }
            __syncthreads();
        } else {
            if (tid == 0) {
                unsigned tgt = 16u * (unsigned)t, v;
                do { asm volatile("ld.acquire.gpu.global.u32 %0, [%1];"
                                  : "=r"(v) : "l"(&g_cnt[bgA])); } while (v < tgt);
                do { asm volatile("ld.acquire.gpu.global.u32 %0, [%1];"
                                  : "=r"(v) : "l"(&g_cnt[bgB])); } while (v < tgt);
            }
            __syncthreads();
            const float2* srcA = &g_hseq[((size_t)(t - 1) * 8 + bgA) * 2048];
            const float2* srcB = &g_hseq[((size_t)(t - 1) * 8 + bgB) * 2048];
            uint32_t dA = smem_u32(hpA), dB = smem_u32(hpB);
            #pragma unroll
            for (int i = 0; i < 4; i++) {
                int c = tid + i * 256;               // 0..1023 chunks of 16B
                cp16(dA + c * 16, srcA + c * 2);
                cp16(dB + c * 16, srcB + c * 2);
            }
            CP_COMMIT();
            CP_WAIT(0);
            __syncthreads();
        }

        phase(hpA, B0A, bgA, t);
        phase(hpB, B0B, bgB, t);
    }
}

// ---------------- fp16 convert of W_fc ----------------
__global__ void k_convB(const float* __restrict__ Wfc) {
    size_t i = (size_t)blockIdx.x * 256 + threadIdx.x;   // float4 index
    float4 v = ((const float4*)Wfc)[i];
    __half2* hi = (__half2*)g_B16;
    hi[2 * i]     = __half2(__float2half_rn(v.x), __float2half_rn(v.y));
    hi[2 * i + 1] = __half2(__float2half_rn(v.z), __float2half_rn(v.w));
}

// ---------------- FC GEMM via mma.sync: C = A16 * B16^T ----------------
#define PITCH   40                     // halves per smem row (80 B, conflict-free)
#define TILEB   (128 * PITCH * 2)      // 10240 B per tile
#define STAGEB  (2 * TILEB)            // A, B

__global__ void __launch_bounds__(256, 2)
k_fcmma(const float* __restrict__ bfc, float* __restrict__ out) {
    extern __shared__ char dsm[];
    float* s_bias = (float*)dsm;                     // 128 floats
    uint32_t sbase = smem_u32(dsm) + 1024;           // tiles base

    int tid = threadIdx.x;
    int l = tid & 31, wid = tid >> 5;
    int m0 = blockIdx.x * 128;
    int v0 = blockIdx.y * 128;
    int mw = (wid >> 2) * 64;
    int nw = (wid & 3) * 32;

    if (tid < 128) s_bias[tid] = bfc[v0 + tid];

    const __half* gsrc[2] = { g_A16 + (size_t)m0 * HID, g_B16 + (size_t)v0 * HID };

    auto load_stage = [&](int s, int kt) {
        #pragma unroll
        for (int i = 0; i < 4; i++) {
            int id = tid + i * 256;          // 0..1023
            int tle = id >> 9;
            int c = id & 511;
            int r = c >> 2;
            int ch = c & 3;
            uint32_t dst = sbase + s * STAGEB + tle * TILEB + r * 80 + ch * 16;
            cp16(dst, gsrc[tle] + (size_t)r * HID + kt * 32 + ch * 8);
        }
    };

    float acc[4][4][4];
    #pragma unroll
    for (int i = 0; i < 4; i++)
        #pragma unroll
        for (int j = 0; j < 4; j++)
            #pragma unroll
            for (int k = 0; k < 4; k++) acc[i][j][k] = 0.f;

    int mat = l >> 3, r8 = l & 7;
    uint32_t a_lane = (uint32_t)((mw + (mat & 1) * 8 + r8) * 80 + (mat >> 1) * 16);
    uint32_t b_lane = (uint32_t)((nw + (mat >> 1) * 8 + r8) * 80 + (mat & 1) * 16) + TILEB;

    load_stage(0, 0);
    CP_COMMIT();

    for (int kt = 0; kt < 16; kt++) {
        int buf = kt & 1;
        if (kt < 15) { load_stage(buf ^ 1, kt + 1); CP_COMMIT(); CP_WAIT(1); }
        else         { CP_WAIT(0); }
        __syncthreads();

        uint32_t sb = sbase + buf * STAGEB;
        #pragma unroll
        for (int ks = 0; ks < 2; ks++) {
            uint32_t ko = ks * 32;
            uint32_t bf[4][2];
            ldm_x4(bf[0][0], bf[0][1], bf[1][0], bf[1][1], sb + b_lane + ko);
            ldm_x4(bf[2][0], bf[2][1], bf[3][0], bf[3][1], sb + b_lane + 16 * 80 + ko);
            uint32_t af[4][4];
            #pragma unroll
            for (int fm = 0; fm < 4; fm++)
                ldm_x4(af[fm][0], af[fm][1], af[fm][2], af[fm][3],
                       sb + a_lane + fm * (16 * 80) + ko);
            #pragma unroll
            for (int fm = 0; fm < 4; fm++)
                #pragma unroll
                for (int fn = 0; fn < 4; fn++)
                    mma16816(acc[fm][fn], af[fm][0], af[fm][1], af[fm][2], af[fm][3],
                             bf[fn][0], bf[fn][1]);
        }
        __syncthreads();
    }

    #pragma unroll
    for (int fm = 0; fm < 4; fm++) {
        #pragma unroll
        for (int fn = 0; fn < 4; fn++) {
            int vloc = nw + fn * 8 + (l & 3) * 2;
            float bv0 = s_bias[vloc];
            float bv1 = s_bias[vloc + 1];
            int m = m0 + mw + fm * 16 + (l >> 2);
            int b = m & (BATCH - 1);
            int t = m >> 6;
            float2* p = (float2*)(out + (size_t)b * SEQ * VOCAB + (size_t)t * VOCAB + v0 + vloc);
            *p = make_float2(acc[fm][fn][0] + bv0, acc[fm][fn][1] + bv1);
            int m2 = m + 8;
            b = m2 & (BATCH - 1);
            t = m2 >> 6;
            p = (float2*)(out + (size_t)b * SEQ * VOCAB + (size_t)t * VOCAB + v0 + vloc);
            *p = make_float2(acc[fm][fn][2] + bv0, acc[fm][fn][3] + bv1);
        }
    }
}

// ---------------- copy h_last from g_hseq[t=511] ----------------
__global__ void k_hid(float* __restrict__ out) {
    int i = blockIdx.x * 256 + threadIdx.x;   // i = b*HID + h
    int b = i >> 9, h = i & 511;
    int bg = b >> 3, p = (b & 7) >> 1, e = b & 1;
    float2 v = g_hseq[((size_t)(511 * 8 + bg) * 4 + p) * 512 + h];
    out[i] = e ? v.y : v.x;
}

// ---------------- launcher ----------------
extern "C" void kernel_launch(void* const* d_in, const int* in_sizes, int n_in,
                              void* d_out, int out_size) {
    const int*   inp = (const int*)d_in[0];
    const float* hid = (const float*)d_in[1];
    const float* Wih = (const float*)d_in[2];
    const float* Whh = (const float*)d_in[3];
    const float* bih = (const float*)d_in[4];
    const float* bhh = (const float*)d_in[5];
    const float* Wfc = (const float*)d_in[6];
    const float* bfc = (const float*)d_in[7];
    float* out = (float*)d_out;

    cudaFuncSetAttribute(k_rnn,   cudaFuncAttributeMaxDynamicSharedMemorySize, 106496);
    cudaFuncSetAttribute(k_fcmma, cudaFuncAttributeMaxDynamicSharedMemorySize, 1024 + 2 * STAGEB);

    k_transpose<<<dim3(VOCAB / 32, HID / 32), dim3(32, 8)>>>(Wih);
    k_gather<<<SEQ * BATCH, 128>>>(inp, bih, bhh);
    k_reset<<<1, 32>>>();
    k_convB<<<(VOCAB * HID / 4) / 256, 256>>>(Wfc);
    k_rnn<<<64, 256, 106496>>>(Whh, hid);
    k_fcmma<<<dim3(MROWS / 128, VOCAB / 128), 256, 1024 + 2 * STAGEB>>>(bfc, out);

    long long logits_elems = (long long)BATCH * SEQ * VOCAB;
    if ((long long)out_size >= logits_elems + (long long)BATCH * HID) {
        k_hid<<<BATCH * HID / 256, 256>>>(out + logits_elems);
    }
}

// round 10
// speedup vs baseline: 1.7621x; 1.7621x over previous
#include <cuda_runtime.h>
#include <cuda_fp16.h>
#include <math.h>
#include <cstdint>

#define VOCAB 4096
#define HID   512
#define BATCH 64
#define SEQ   512
#define MROWS (SEQ * BATCH)

typedef unsigned long long u64;

// ---------------- scratch (static device globals; no allocation) ----------------
__device__ float    g_WihT[VOCAB * HID];          // 8 MB  : W_ih transposed [V,H]
__device__ float    g_xproj[MROWS * HID];         // 64 MB : x_proj, layout [T,B,H]
__device__ float2   g_hseq[SEQ * 8 * 4 * 512];    // 64 MB : h states, pair-interleaved
__device__ __half   g_A16[MROWS * HID];           // 32 MB : fp16 of out_h
__device__ __half   g_B16[VOCAB * HID];           // 4 MB  : fp16 of W_fc
__device__ unsigned g_cnt[8];                     // per-batch-group barrier counters

// ======================= helpers =======================
__device__ __forceinline__ uint32_t smem_u32(const void* p) {
    uint32_t a;
    asm("{ .reg .u64 t; cvta.to.shared.u64 t, %1; cvt.u32.u64 %0, t; }" : "=r"(a) : "l"(p));
    return a;
}
__device__ __forceinline__ void cp16(uint32_t dst, const void* src) {
    asm volatile("cp.async.cg.shared.global [%0], [%1], 16;" :: "r"(dst), "l"(src));
}
#define CP_COMMIT() asm volatile("cp.async.commit_group;" ::: "memory")
#define CP_WAIT(n)  asm volatile("cp.async.wait_group %0;" :: "n"(n) : "memory")

__device__ __forceinline__ void ldm_x4(uint32_t& r0, uint32_t& r1, uint32_t& r2,
                                       uint32_t& r3, uint32_t a) {
    asm volatile("ldmatrix.sync.aligned.m8n8.x4.shared.b16 {%0,%1,%2,%3}, [%4];"
                 : "=r"(r0), "=r"(r1), "=r"(r2), "=r"(r3) : "r"(a));
}
__device__ __forceinline__ void mma16816(float* c, uint32_t a0, uint32_t a1,
                                         uint32_t a2, uint32_t a3,
                                         uint32_t b0, uint32_t b1) {
    asm volatile("mma.sync.aligned.m16n8k16.row.col.f32.f16.f16.f32 "
                 "{%0,%1,%2,%3}, {%4,%5,%6,%7}, {%8,%9}, {%0,%1,%2,%3};"
                 : "+f"(c[0]), "+f"(c[1]), "+f"(c[2]), "+f"(c[3])
                 : "r"(a0), "r"(a1), "r"(a2), "r"(a3), "r"(b0), "r"(b1));
}

// ---- packed fp32x2 ----
__device__ __forceinline__ u64 pack2(float x, float y) {
    u64 r; asm("mov.b64 %0, {%1, %2};" : "=l"(r) : "f"(x), "f"(y)); return r;
}
__device__ __forceinline__ float2 unpack2(u64 v) {
    float2 f; asm("mov.b64 {%0, %1}, %2;" : "=f"(f.x), "=f"(f.y) : "l"(v)); return f;
}
__device__ __forceinline__ void fma2(u64& acc, u64 a, u64 b) {
    asm("fma.rn.f32x2 %0, %1, %2, %0;" : "+l"(acc) : "l"(a), "l"(b));
}
__device__ __forceinline__ u64 add2(u64 a, u64 b) {
    u64 r; asm("add.rn.f32x2 %0, %1, %2;" : "=l"(r) : "l"(a), "l"(b)); return r;
}

// ---------------- transpose W_ih [H,V] -> g_WihT [V,H] ----------------
__global__ void k_transpose(const float* __restrict__ Wih) {
    __shared__ float tile[32][33];
    int v0 = blockIdx.x * 32;
    int h0 = blockIdx.y * 32;
    int tx = threadIdx.x, ty = threadIdx.y;   // 32 x 8
    #pragma unroll
    for (int i = ty; i < 32; i += 8)
        tile[i][tx] = Wih[(h0 + i) * VOCAB + v0 + tx];
    __syncthreads();
    #pragma unroll
    for (int i = ty; i < 32; i += 8)
        g_WihT[(v0 + i) * HID + h0 + tx] = tile[tx][i];
}

// ---------------- gather + bias ----------------
__global__ void k_gather(const int* __restrict__ inp,
                         const float* __restrict__ b_ih,
                         const float* __restrict__ b_hh) {
    int row = blockIdx.x;              // row = t*BATCH + b
    int t = row / BATCH;
    int b = row % BATCH;
    int tok = inp[b * SEQ + t];
    const float4* src = (const float4*)&g_WihT[tok * HID];
    const float4* bi4 = (const float4*)b_ih;
    const float4* bh4 = (const float4*)b_hh;
    float4* dst = (float4*)&g_xproj[row * HID];
    int i = threadIdx.x;               // 128 threads
    float4 v = src[i];
    float4 bi = bi4[i], bh = bh4[i];
    v.x += bi.x + bh.x;  v.y += bi.y + bh.y;
    v.z += bi.z + bh.z;  v.w += bi.w + bh.w;
    dst[i] = v;
}

__global__ void k_reset() {
    if (threadIdx.x < 8) g_cnt[threadIdx.x] = 0;
}

// ---------------- recurrence v5: R7 structure, W_hh in registers ----------------
// 128 CTAs = 8 batch-groups x 16 j-slices(32). 128 threads = 4 warps, warp w owns
// k in [w*128,(w+1)*128). W slice (128 floats/thread) lives in registers for all
// 512 steps. smem: hp float2[4*512] 16KB + part u64[16*32] 4KB = 20KB.
extern "C" __global__ void __launch_bounds__(128, 1)
k_rnn(const float* __restrict__ Whh, const float* __restrict__ h0g) {
    extern __shared__ float sm[];
    float2* hp   = (float2*)sm;                 // [pair][k] 4*512
    u64*    part = (u64*)(hp + 4 * 512);        // [warp*4+pair][jl]

    int bx = blockIdx.x;
    int bg = bx & 7;
    int jg = bx >> 3;
    int B0 = bg * 8;
    int J0 = jg * 32;
    int tid = threadIdx.x;
    int w = tid >> 5, jl = tid & 31;
    int kbase = w * 128;

    // W_hh slice into registers: wreg[i] = Whh[(J0+jl)][kbase+i], i = 0..127
    float wreg[128];
    {
        const float4* wsrc = (const float4*)(Whh + (size_t)(J0 + jl) * HID + kbase);
        #pragma unroll
        for (int q = 0; q < 32; q++) {
            float4 v = wsrc[q];
            wreg[4 * q + 0] = v.x;  wreg[4 * q + 1] = v.y;
            wreg[4 * q + 2] = v.z;  wreg[4 * q + 3] = v.w;
        }
    }

    // per-thread reduce-role indices (also used for x prefetch)
    int rp = tid >> 5, rj = tid & 31;
    size_t xstride = (size_t)BATCH * HID;
    size_t xb0 = (size_t)(B0 + 2 * rp) * HID + J0 + rj;

    unsigned target = 0;
    for (int t = 0; t < SEQ; t++) {
        // prefetch x_proj for the reduce phase (independent of h)
        size_t xb = (size_t)t * xstride + xb0;
        float xv0 = g_xproj[xb];
        float xv1 = g_xproj[xb + HID];

        // ---- stage h_{t-1} pair-interleaved into smem ----
        if (t == 0) {
            for (int idx = tid; idx < 2048; idx += 128) {
                int p = idx >> 9, k = idx & 511;
                hp[p * 512 + k] = make_float2(h0g[(B0 + 2 * p) * HID + k],
                                              h0g[(B0 + 2 * p + 1) * HID + k]);
            }
        } else {
            const float4* src = (const float4*)&g_hseq[((size_t)(t - 1) * 8 + bg) * 2048];
            float4* dst = (float4*)hp;
            #pragma unroll
            for (int i = 0; i < 8; i++)
                dst[tid + i * 128] = src[tid + i * 128];
        }
        __syncthreads();

        // ---- packed partial dot products, W from registers ----
        u64 accA[4] = {0, 0, 0, 0}, accB[4] = {0, 0, 0, 0};
        const ulonglong2* h2 = ((const ulonglong2*)hp) + (kbase >> 1);
        #pragma unroll
        for (int i = 0; i < 64; i++) {
            u64 w00 = pack2(wreg[2 * i], wreg[2 * i]);
            u64 w11 = pack2(wreg[2 * i + 1], wreg[2 * i + 1]);
            ulonglong2 hv0 = h2[0 * 256 + i];
            ulonglong2 hv1 = h2[1 * 256 + i];
            ulonglong2 hv2 = h2[2 * 256 + i];
            ulonglong2 hv3 = h2[3 * 256 + i];
            fma2(accA[0], hv0.x, w00);  fma2(accB[0], hv0.y, w11);
            fma2(accA[1], hv1.x, w00);  fma2(accB[1], hv1.y, w11);
            fma2(accA[2], hv2.x, w00);  fma2(accB[2], hv2.y, w11);
            fma2(accA[3], hv3.x, w00);  fma2(accB[3], hv3.y, w11);
        }
        #pragma unroll
        for (int p = 0; p < 4; p++)
            part[(w * 4 + p) * 32 + jl] = add2(accA[p], accB[p]);
        __syncthreads();

        // ---- reduce across 4 warps, tanh, store ----
        {
            u64 s0 = add2(part[(0 + rp) * 32 + rj], part[(4 + rp) * 32 + rj]);
            u64 s1 = add2(part[(8 + rp) * 32 + rj], part[(12 + rp) * 32 + rj]);
            float2 s = unpack2(add2(s0, s1));
            float r0 = tanhf(s.x + xv0);
            float r1 = tanhf(s.y + xv1);
            g_hseq[((size_t)(t * 8 + bg) * 4 + rp) * 512 + (J0 + rj)] = make_float2(r0, r1);
            g_A16[xb]       = __float2half_rn(r0);
            g_A16[xb + HID] = __float2half_rn(r1);
        }
        __syncthreads();

        // ---- group barrier (16 CTAs): release-atomic arrive + acquire-poll ----
        if (t < SEQ - 1) {
            target += 16;
            if (tid == 0) {
                asm volatile("red.release.gpu.global.add.u32 [%0], %1;"
                             :: "l"(&g_cnt[bg]), "r"(1u) : "memory");
                unsigned v;
                do {
                    asm volatile("ld.acquire.gpu.global.u32 %0, [%1];"
                                 : "=r"(v) : "l"(&g_cnt[bg]));
                } while (v < target);
            }
            __syncthreads();
        }
    }
}

// ---------------- fp16 convert of W_fc ----------------
__global__ void k_convB(const float* __restrict__ Wfc) {
    size_t i = (size_t)blockIdx.x * 256 + threadIdx.x;   // float4 index
    float4 v = ((const float4*)Wfc)[i];
    __half2* hi = (__half2*)g_B16;
    hi[2 * i]     = __half2(__float2half_rn(v.x), __float2half_rn(v.y));
    hi[2 * i + 1] = __half2(__float2half_rn(v.z), __float2half_rn(v.w));
}

// ---------------- FC GEMM via mma.sync: C = A16 * B16^T ----------------
// CTA tile 128x128, 8 warps (2m x 4n), k-tile 32, 3-stage cp.async pipeline,
// ONE __syncthreads per k-iter, 2 CTAs/SM, ldmatrix fragment loads.
#define PITCH   40                     // halves per smem row (80 B, conflict-free)
#define TILEB   (128 * PITCH * 2)      // 10240 B per tile
#define STAGEB  (2 * TILEB)            // A, B
#define NSTAGE  3

__global__ void __launch_bounds__(256, 2)
k_fcmma(const float* __restrict__ bfc, float* __restrict__ out) {
    extern __shared__ char dsm[];
    float* s_bias = (float*)dsm;                     // 128 floats
    uint32_t sbase = smem_u32(dsm) + 1024;           // tiles base

    int tid = threadIdx.x;
    int l = tid & 31, wid = tid >> 5;
    int m0 = blockIdx.x * 128;
    int v0 = blockIdx.y * 128;
    int mw = (wid >> 2) * 64;
    int nw = (wid & 3) * 32;

    if (tid < 128) s_bias[tid] = bfc[v0 + tid];

    const __half* gsrc[2] = { g_A16 + (size_t)m0 * HID, g_B16 + (size_t)v0 * HID };

    auto load_stage = [&](int s, int kt) {
        #pragma unroll
        for (int i = 0; i < 4; i++) {
            int id = tid + i * 256;          // 0..1023
            int tle = id >> 9;
            int c = id & 511;
            int r = c >> 2;
            int ch = c & 3;
            uint32_t dst = sbase + s * STAGEB + tle * TILEB + r * 80 + ch * 16;
            cp16(dst, gsrc[tle] + (size_t)r * HID + kt * 32 + ch * 8);
        }
    };

    float acc[4][4][4];
    #pragma unroll
    for (int i = 0; i < 4; i++)
        #pragma unroll
        for (int j = 0; j < 4; j++)
            #pragma unroll
            for (int k = 0; k < 4; k++) acc[i][j][k] = 0.f;

    int mat = l >> 3, r8 = l & 7;
    uint32_t a_lane = (uint32_t)((mw + (mat & 1) * 8 + r8) * 80 + (mat >> 1) * 16);
    uint32_t b_lane = (uint32_t)((nw + (mat >> 1) * 8 + r8) * 80 + (mat & 1) * 16) + TILEB;

    load_stage(0, 0);
    CP_COMMIT();
    load_stage(1, 1);
    CP_COMMIT();

    int buf = 0;
    for (int kt = 0; kt < 16; kt++) {
        if (kt < 15) { CP_WAIT(1); } else { CP_WAIT(0); }
        __syncthreads();
        if (kt + 2 < 16) { load_stage((buf + 2) % NSTAGE, kt + 2); CP_COMMIT(); }

        uint32_t sb = sbase + buf * STAGEB;
        #pragma unroll
        for (int ks = 0; ks < 2; ks++) {
            uint32_t ko = ks * 32;
            uint32_t bf[4][2];
            ldm_x4(bf[0][0], bf[0][1], bf[1][0], bf[1][1], sb + b_lane + ko);
            ldm_x4(bf[2][0], bf[2][1], bf[3][0], bf[3][1], sb + b_lane + 16 * 80 + ko);
            uint32_t af[4][4];
            #pragma unroll
            for (int fm = 0; fm < 4; fm++)
                ldm_x4(af[fm][0], af[fm][1], af[fm][2], af[fm][3],
                       sb + a_lane + fm * (16 * 80) + ko);
            #pragma unroll
            for (int fm = 0; fm < 4; fm++)
                #pragma unroll
                for (int fn = 0; fn < 4; fn++)
                    mma16816(acc[fm][fn], af[fm][0], af[fm][1], af[fm][2], af[fm][3],
                             bf[fn][0], bf[fn][1]);
        }
        buf = (buf + 1) % NSTAGE;
    }

    #pragma unroll
    for (int fm = 0; fm < 4; fm++) {
        #pragma unroll
        for (int fn = 0; fn < 4; fn++) {
            int vloc = nw + fn * 8 + (l & 3) * 2;
            float bv0 = s_bias[vloc];
            float bv1 = s_bias[vloc + 1];
            int m = m0 + mw + fm * 16 + (l >> 2);
            int b = m & (BATCH - 1);
            int t = m >> 6;
            float2* p = (float2*)(out + (size_t)b * SEQ * VOCAB + (size_t)t * VOCAB + v0 + vloc);
            *p = make_float2(acc[fm][fn][0] + bv0, acc[fm][fn][1] + bv1);
            int m2 = m + 8;
            b = m2 & (BATCH - 1);
            t = m2 >> 6;
            p = (float2*)(out + (size_t)b * SEQ * VOCAB + (size_t)t * VOCAB + v0 + vloc);
            *p = make_float2(acc[fm][fn][2] + bv0, acc[fm][fn][3] + bv1);
        }
    }
}

// ---------------- copy h_last from g_hseq[t=511] ----------------
__global__ void k_hid(float* __restrict__ out) {
    int i = blockIdx.x * 256 + threadIdx.x;   // i = b*HID + h
    int b = i >> 9, h = i & 511;
    int bg = b >> 3, p = (b & 7) >> 1, e = b & 1;
    float2 v = g_hseq[((size_t)(511 * 8 + bg) * 4 + p) * 512 + h];
    out[i] = e ? v.y : v.x;
}

// ---------------- launcher ----------------
extern "C" void kernel_launch(void* const* d_in, const int* in_sizes, int n_in,
                              void* d_out, int out_size) {
    const int*   inp = (const int*)d_in[0];
    const float* hid = (const float*)d_in[1];
    const float* Wih = (const float*)d_in[2];
    const float* Whh = (const float*)d_in[3];
    const float* bih = (const float*)d_in[4];
    const float* bhh = (const float*)d_in[5];
    const float* Wfc = (const float*)d_in[6];
    const float* bfc = (const float*)d_in[7];
    float* out = (float*)d_out;

    cudaFuncSetAttribute(k_rnn,   cudaFuncAttributeMaxDynamicSharedMemorySize, 20480);
    cudaFuncSetAttribute(k_fcmma, cudaFuncAttributeMaxDynamicSharedMemorySize, 1024 + NSTAGE * STAGEB);

    // k_rnn at launch slot 4 — the slot ncu has been profiling
    k_transpose<<<dim3(VOCAB / 32, HID / 32), dim3(32, 8)>>>(Wih);
    k_gather<<<SEQ * BATCH, 128>>>(inp, bih, bhh);
    k_reset<<<1, 32>>>();
    k_rnn<<<128, 128, 20480>>>(Whh, hid);
    k_convB<<<(VOCAB * HID / 4) / 256, 256>>>(Wfc);
    k_fcmma<<<dim3(MROWS / 128, VOCAB / 128), 256, 1024 + NSTAGE * STAGEB>>>(bfc, out);

    long long logits_elems = (long long)BATCH * SEQ * VOCAB;
    if ((long long)out_size >= logits_elems + (long long)BATCH * HID) {
        k_hid<<<BATCH * HID / 256, 256>>>(out + logits_elems);
    }
}